// round 3
// baseline (speedup 1.0000x reference)
#include <cuda_runtime.h>
#include <math.h>

#define BATCH 8
#define SEQ   1024
#define DEMB  1024
#define NHEAD 16
#define DHEAD 64
#define MROWS (BATCH*SEQ)   // 8192

// Scratch (allocation-free rule: device globals)
__device__ float g_Q[(size_t)BATCH*NHEAD*SEQ*DHEAD];
__device__ float g_K[(size_t)BATCH*NHEAD*SEQ*DHEAD];
__device__ float g_V[(size_t)BATCH*NHEAD*SEQ*DHEAD];
__device__ float g_O[(size_t)MROWS*DEMB];

// ---------------------------------------------------------------------------
// QKV GEMM: X[8192,1024] @ Wqkv[1024,3072] + b_qkv
// Epilogue scatters into Q/K/V with layout [B,H,N,64].
// qkv packing: col c -> h = c/192, dd = (c%192)/3, which = c%3
// ---------------------------------------------------------------------------
__global__ __launch_bounds__(256) void qkv_gemm_kernel(
    const float* __restrict__ X, const float* __restrict__ W,
    const float* __restrict__ bias)
{
    __shared__ float As[16][128];
    __shared__ float Bs[16][128];
    const int bm  = blockIdx.y * 128;
    const int bn  = blockIdx.x * 128;
    const int tid = threadIdx.x;
    const int tx  = tid & 15;
    const int ty  = tid >> 4;

    float acc[8][8];
    #pragma unroll
    for (int i = 0; i < 8; i++)
        #pragma unroll
        for (int j = 0; j < 8; j++) acc[i][j] = 0.f;

    for (int k0 = 0; k0 < 1024; k0 += 16) {
        #pragma unroll
        for (int i = 0; i < 2; i++) {
            int f   = tid + i * 256;
            int row = f >> 2;
            int c4  = (f & 3) << 2;
            float4 v = *(const float4*)(X + (size_t)(bm + row) * 1024 + k0 + c4);
            As[c4 + 0][row] = v.x; As[c4 + 1][row] = v.y;
            As[c4 + 2][row] = v.z; As[c4 + 3][row] = v.w;
        }
        #pragma unroll
        for (int i = 0; i < 2; i++) {
            int f   = tid + i * 256;
            int row = f >> 5;
            int col = (f & 31) << 2;
            *(float4*)(&Bs[row][col]) =
                *(const float4*)(W + (size_t)(k0 + row) * 3072 + bn + col);
        }
        __syncthreads();
        #pragma unroll
        for (int k = 0; k < 16; k++) {
            float a[8], b[8];
            *(float4*)(a)     = *(const float4*)(&As[k][ty * 4]);
            *(float4*)(a + 4) = *(const float4*)(&As[k][ty * 4 + 64]);
            *(float4*)(b)     = *(const float4*)(&Bs[k][tx * 4]);
            *(float4*)(b + 4) = *(const float4*)(&Bs[k][tx * 4 + 64]);
            #pragma unroll
            for (int i = 0; i < 8; i++)
                #pragma unroll
                for (int j = 0; j < 8; j++)
                    acc[i][j] += a[i] * b[j];
        }
        __syncthreads();
    }

    #pragma unroll
    for (int i = 0; i < 8; i++) {
        int gr = bm + ty * 4 + ((i & 4) << 4) + (i & 3);   // global row (b*1024+n)
        int bb = gr >> 10;
        int nn = gr & 1023;
        #pragma unroll
        for (int j = 0; j < 8; j++) {
            int gc = bn + tx * 4 + ((j & 4) << 4) + (j & 3); // global col in [0,3072)
            float v = acc[i][j] + bias[gc];
            int h  = gc / 192;
            int r  = gc - h * 192;
            int dd = r / 3;
            int which = r - dd * 3;
            size_t idx = (((size_t)(bb * NHEAD + h)) * SEQ + nn) * DHEAD + dd;
            if      (which == 0) g_Q[idx] = v;
            else if (which == 1) g_K[idx] = v;
            else                 g_V[idx] = v;
        }
    }
}

// ---------------------------------------------------------------------------
// Flash attention (fp32, online softmax). 1 block = 128 queries of one (b,h).
// score = q.k (NO 1/sqrt(d) inside softmax); final scale = 1/(32 * l).
// Writes O as [B*N, D] with column = h*64 + dd.
// ---------------------------------------------------------------------------
__global__ __launch_bounds__(128) void flash_attn_kernel()
{
    const int bh   = blockIdx.x;       // 0..127
    const int qt   = blockIdx.y;       // 0..7
    const int tid  = threadIdx.x;
    const int qrow = qt * 128 + tid;

    const float* __restrict__ Qb = g_Q + (size_t)bh * SEQ * DHEAD;
    const float* __restrict__ Kb = g_K + (size_t)bh * SEQ * DHEAD;
    const float* __restrict__ Vb = g_V + (size_t)bh * SEQ * DHEAD;

    float q[64];
    {
        const float4* qp = (const float4*)(Qb + (size_t)qrow * DHEAD);
        #pragma unroll
        for (int c = 0; c < 16; c++) {
            float4 t = qp[c];
            q[4*c] = t.x; q[4*c+1] = t.y; q[4*c+2] = t.z; q[4*c+3] = t.w;
        }
    }

    float o[64];
    #pragma unroll
    for (int i = 0; i < 64; i++) o[i] = 0.f;
    float m = -1e30f, l = 0.f;

    __shared__ float Ks[16][64];
    __shared__ float Vs[16][64];

    for (int t = 0; t < SEQ / 16; t++) {
        __syncthreads();
        {
            const float4* kg = (const float4*)(Kb + (size_t)t * 16 * DHEAD);
            const float4* vg = (const float4*)(Vb + (size_t)t * 16 * DHEAD);
            float4* ks = (float4*)(&Ks[0][0]);
            float4* vs = (float4*)(&Vs[0][0]);
            ks[tid]       = kg[tid];
            ks[tid + 128] = kg[tid + 128];
            vs[tid]       = vg[tid];
            vs[tid + 128] = vg[tid + 128];
        }
        __syncthreads();

        float s[16];
        #pragma unroll
        for (int j = 0; j < 16; j++) {
            float s0 = 0.f, s1 = 0.f, s2 = 0.f, s3 = 0.f;
            const float4* kr = (const float4*)(&Ks[j][0]);
            #pragma unroll
            for (int c = 0; c < 16; c++) {
                float4 kv = kr[c];
                s0 += q[4*c]     * kv.x;
                s1 += q[4*c + 1] * kv.y;
                s2 += q[4*c + 2] * kv.z;
                s3 += q[4*c + 3] * kv.w;
            }
            s[j] = (s0 + s1) + (s2 + s3);
        }

        float tmax = s[0];
        #pragma unroll
        for (int j = 1; j < 16; j++) tmax = fmaxf(tmax, s[j]);
        float nm    = fmaxf(m, tmax);
        float alpha = __expf(m - nm);
        float psum  = 0.f;
        #pragma unroll
        for (int j = 0; j < 16; j++) { s[j] = __expf(s[j] - nm); psum += s[j]; }
        l = l * alpha + psum;
        m = nm;

        #pragma unroll
        for (int dd = 0; dd < 64; dd++) o[dd] *= alpha;
        #pragma unroll
        for (int j = 0; j < 16; j++) {
            float pj = s[j];
            const float4* vr = (const float4*)(&Vs[j][0]);
            #pragma unroll
            for (int c = 0; c < 16; c++) {
                float4 vv = vr[c];
                o[4*c]     += pj * vv.x;
                o[4*c + 1] += pj * vv.y;
                o[4*c + 2] += pj * vv.z;
                o[4*c + 3] += pj * vv.w;
            }
        }
    }

    // att = softmax/32  ->  out = (1/32) * (o / l)
    const float inv = 1.0f / (l * 32.0f);
    const int bb = bh >> 4;
    const int hh = bh & 15;
    float4* op = (float4*)(g_O + ((size_t)(bb * SEQ + qrow)) * DEMB + hh * DHEAD);
    #pragma unroll
    for (int c = 0; c < 16; c++)
        op[c] = make_float4(o[4*c] * inv, o[4*c+1] * inv, o[4*c+2] * inv, o[4*c+3] * inv);
}

// ---------------------------------------------------------------------------
// Proj GEMM: O[8192,1024] @ Wproj[1024,1024] + b_proj -> d_out
// ---------------------------------------------------------------------------
__global__ __launch_bounds__(256) void proj_gemm_kernel(
    const float* __restrict__ W, const float* __restrict__ bias,
    float* __restrict__ out)
{
    __shared__ float As[16][128];
    __shared__ float Bs[16][128];
    const int bm  = blockIdx.y * 128;
    const int bn  = blockIdx.x * 128;
    const int tid = threadIdx.x;
    const int tx  = tid & 15;
    const int ty  = tid >> 4;

    float acc[8][8];
    #pragma unroll
    for (int i = 0; i < 8; i++)
        #pragma unroll
        for (int j = 0; j < 8; j++) acc[i][j] = 0.f;

    for (int k0 = 0; k0 < 1024; k0 += 16) {
        #pragma unroll
        for (int i = 0; i < 2; i++) {
            int f   = tid + i * 256;
            int row = f >> 2;
            int c4  = (f & 3) << 2;
            float4 v = *(const float4*)(g_O + (size_t)(bm + row) * 1024 + k0 + c4);
            As[c4 + 0][row] = v.x; As[c4 + 1][row] = v.y;
            As[c4 + 2][row] = v.z; As[c4 + 3][row] = v.w;
        }
        #pragma unroll
        for (int i = 0; i < 2; i++) {
            int f   = tid + i * 256;
            int row = f >> 5;
            int col = (f & 31) << 2;
            *(float4*)(&Bs[row][col]) =
                *(const float4*)(W + (size_t)(k0 + row) * 1024 + bn + col);
        }
        __syncthreads();
        #pragma unroll
        for (int k = 0; k < 16; k++) {
            float a[8], b[8];
            *(float4*)(a)     = *(const float4*)(&As[k][ty * 4]);
            *(float4*)(a + 4) = *(const float4*)(&As[k][ty * 4 + 64]);
            *(float4*)(b)     = *(const float4*)(&Bs[k][tx * 4]);
            *(float4*)(b + 4) = *(const float4*)(&Bs[k][tx * 4 + 64]);
            #pragma unroll
            for (int i = 0; i < 8; i++)
                #pragma unroll
                for (int j = 0; j < 8; j++)
                    acc[i][j] += a[i] * b[j];
        }
        __syncthreads();
    }

    #pragma unroll
    for (int i = 0; i < 8; i++) {
        int gr = bm + ty * 4 + ((i & 4) << 4) + (i & 3);
        #pragma unroll
        for (int j = 0; j < 8; j++) {
            int gc = bn + tx * 4 + ((j & 4) << 4) + (j & 3);
            out[(size_t)gr * 1024 + gc] = acc[i][j] + bias[gc];
        }
    }
}

// ---------------------------------------------------------------------------
extern "C" void kernel_launch(void* const* d_in, const int* in_sizes, int n_in,
                              void* d_out, int out_size)
{
    const float* x      = (const float*)d_in[0];
    const float* w_qkv  = (const float*)d_in[1];
    const float* b_qkv  = (const float*)d_in[2];
    const float* w_proj = (const float*)d_in[3];
    const float* b_proj = (const float*)d_in[4];
    float* out = (float*)d_out;

    dim3 g1(3072 / 128, MROWS / 128);   // 24 x 64
    qkv_gemm_kernel<<<g1, 256>>>(x, w_qkv, b_qkv);

    dim3 g2(BATCH * NHEAD, SEQ / 128);  // 128 x 8
    flash_attn_kernel<<<g2, 128>>>();

    dim3 g3(1024 / 128, MROWS / 128);   // 8 x 64
    proj_gemm_kernel<<<g3, 256>>>(w_proj, b_proj, out);
}

// round 7
// speedup vs baseline: 1.2728x; 1.2728x over previous
#include <cuda_runtime.h>
#include <cuda_bf16.h>
#include <stdint.h>
#include <math.h>

#define BATCH 8
#define SEQ   1024
#define DEMB  1024
#define NHEAD 16
#define DHEAD 64
#define MROWS (BATCH*SEQ)   // 8192

// ------------------------- scratch (device globals) -------------------------
__device__ float g_Q[(size_t)BATCH*NHEAD*SEQ*DHEAD];
__device__ float g_K[(size_t)BATCH*NHEAD*SEQ*DHEAD];
__device__ float g_V[(size_t)BATCH*NHEAD*SEQ*DHEAD];

__device__ __align__(16) __nv_bfloat16 g_Xhi[(size_t)MROWS*DEMB];
__device__ __align__(16) __nv_bfloat16 g_Xlo[(size_t)MROWS*DEMB];
__device__ __align__(16) __nv_bfloat16 g_WqThi[(size_t)3072*1024];
__device__ __align__(16) __nv_bfloat16 g_WqTlo[(size_t)3072*1024];
__device__ __align__(16) __nv_bfloat16 g_WpThi[(size_t)1024*1024];
__device__ __align__(16) __nv_bfloat16 g_WpTlo[(size_t)1024*1024];
__device__ __align__(16) __nv_bfloat16 g_Ohi[(size_t)MROWS*DEMB];
__device__ __align__(16) __nv_bfloat16 g_Olo[(size_t)MROWS*DEMB];

// ------------------------- helpers -------------------------
__device__ __forceinline__ void mma_bf16(float* d, const uint32_t* a, const uint32_t* b) {
    asm volatile("mma.sync.aligned.m16n8k16.row.col.f32.bf16.bf16.f32 "
                 "{%0,%1,%2,%3}, {%4,%5,%6,%7}, {%8,%9}, {%0,%1,%2,%3};"
                 : "+f"(d[0]), "+f"(d[1]), "+f"(d[2]), "+f"(d[3])
                 : "r"(a[0]), "r"(a[1]), "r"(a[2]), "r"(a[3]), "r"(b[0]), "r"(b[1]));
}
__device__ __forceinline__ void split2(float v, __nv_bfloat16& h, __nv_bfloat16& l) {
    h = __float2bfloat16(v);
    l = __float2bfloat16(v - __bfloat162float(h));
}

// ------------------------- conversion kernels -------------------------
// NOTE: all device-global scratch pointers are taken INSIDE device code.
__global__ __launch_bounds__(256) void cvt_x_kernel(const float4* __restrict__ X)
{
    __nv_bfloat162* hi = (__nv_bfloat162*)g_Xhi;
    __nv_bfloat162* lo = (__nv_bfloat162*)g_Xlo;
    int i = blockIdx.x * 256 + threadIdx.x;   // over 2M float4
    float4 v = X[i];
    __nv_bfloat16 h0,l0,h1,l1,h2,l2,h3,l3;
    split2(v.x,h0,l0); split2(v.y,h1,l1); split2(v.z,h2,l2); split2(v.w,h3,l3);
    hi[2*i]   = __nv_bfloat162(h0,h1); hi[2*i+1] = __nv_bfloat162(h2,h3);
    lo[2*i]   = __nv_bfloat162(l0,l1); lo[2*i+1] = __nv_bfloat162(l2,l3);
}

// W [1024(k), ncols(n)] -> WT hi/lo [ncols, 1024] (n rows, k contiguous)
// WSEL 0: w_qkv (ncols=3072) -> g_WqT*,  WSEL 1: w_proj (ncols=1024) -> g_WpT*
template<int WSEL>
__global__ __launch_bounds__(256) void cvt_wT_kernel(const float* __restrict__ W)
{
    const int ncols = (WSEL == 0) ? 3072 : 1024;
    __nv_bfloat16* hiT = (WSEL == 0) ? g_WqThi : g_WpThi;
    __nv_bfloat16* loT = (WSEL == 0) ? g_WqTlo : g_WpTlo;

    __shared__ float t[32][33];
    const int n0 = blockIdx.x * 32, k0 = blockIdx.y * 32;
    const int tx = threadIdx.x, ty = threadIdx.y;   // (32, 8)
    #pragma unroll
    for (int r = ty; r < 32; r += 8)
        t[r][tx] = W[(size_t)(k0 + r) * ncols + n0 + tx];
    __syncthreads();
    #pragma unroll
    for (int rr = ty; rr < 32; rr += 8) {
        float v = t[tx][rr];
        __nv_bfloat16 h, l; split2(v, h, l);
        size_t o = (size_t)(n0 + rr) * 1024 + k0 + tx;
        hiT[o] = h; loT[o] = l;
    }
}

// ------------------------- mma.sync split-bf16 GEMM -------------------------
// C[128x128 tile] = Ahi*Bhi + Ahi*Blo + Alo*Bhi over K=1024 (3 passes x 16 chunks of K=64)
// A: [M,1024] bf16 K-contiguous. B(=W^T): [N,1024] bf16 K-contiguous.
// 256 thr, 8 warps 4(m) x 2(n); warp tile 32x64; mma m16n8k16.
#define KC   64
#define SKC  72          // padded smem row stride (elements); 144 B rows
#define NCH  48          // 3 passes x 16 chunks

template<int MODE>   // 0: qkv (A=X, B=WqT, scatter epilogue), 1: proj (A=O, B=WpT, store)
__global__ __launch_bounds__(256, 1) void gemm_bf16_kernel(
    const float* __restrict__ bias, float* __restrict__ out)
{
    // device-global operands resolved in device code (correct addresses)
    const __nv_bfloat16* __restrict__ Ahi = (MODE == 0) ? g_Xhi   : g_Ohi;
    const __nv_bfloat16* __restrict__ Alo = (MODE == 0) ? g_Xlo   : g_Olo;
    const __nv_bfloat16* __restrict__ Bhi = (MODE == 0) ? g_WqThi : g_WpThi;
    const __nv_bfloat16* __restrict__ Blo = (MODE == 0) ? g_WqTlo : g_WpTlo;

    __shared__ __align__(16) __nv_bfloat16 sA[128 * SKC];
    __shared__ __align__(16) __nv_bfloat16 sB[128 * SKC];

    const int tid  = threadIdx.x;
    const int wid  = tid >> 5, lane = tid & 31;
    const int wm   = wid & 3;        // m-warp 0..3
    const int wn   = wid >> 2;       // n-warp 0..1
    const int bn   = blockIdx.x * 128;
    const int bm   = blockIdx.y * 128;

    float acc[2][8][4];
    #pragma unroll
    for (int mt = 0; mt < 2; mt++)
        #pragma unroll
        for (int n = 0; n < 8; n++)
            #pragma unroll
            for (int c = 0; c < 4; c++) acc[mt][n][c] = 0.f;

    // per-chunk register prefetch: 4 uint4 (32 bf16) per matrix per thread
    uint4 ra[4], rb[4];
    auto issue_loads = [&](int i) {
        const int p  = i >> 4;                  // 0: hi*hi, 1: hi*lo, 2: lo*hi
        const int k0 = (i & 15) * KC;
        const __nv_bfloat16* Ap = (p == 2) ? Alo : Ahi;
        const __nv_bfloat16* Bp = (p == 1) ? Blo : Bhi;
        #pragma unroll
        for (int q = 0; q < 4; q++) {
            int idx = q * 256 + tid;            // 0..1023
            int row = idx >> 3;                 // 0..127
            int col = (idx & 7) * 8;            // 0..56
            ra[q] = *(const uint4*)(Ap + (size_t)(bm + row) * 1024 + k0 + col);
            rb[q] = *(const uint4*)(Bp + (size_t)(bn + row) * 1024 + k0 + col);
        }
    };
    issue_loads(0);

    for (int i = 0; i < NCH; i++) {
        __syncthreads();                        // previous chunk's reads complete
        #pragma unroll
        for (int q = 0; q < 4; q++) {
            int idx = q * 256 + tid;
            int row = idx >> 3;
            int col = (idx & 7) * 8;
            *(uint4*)(sA + row * SKC + col) = ra[q];
            *(uint4*)(sB + row * SKC + col) = rb[q];
        }
        if (i + 1 < NCH) issue_loads(i + 1);    // LDG latency hidden by compute below
        __syncthreads();

        #pragma unroll
        for (int ks = 0; ks < 4; ks++) {
            const int kb = ks * 16 + (lane & 3) * 2;   // this thread's k within chunk
            uint32_t afr[2][4];
            #pragma unroll
            for (int mt = 0; mt < 2; mt++) {
                int r0 = wm * 32 + mt * 16 + (lane >> 2);
                afr[mt][0] = *(const uint32_t*)(sA + (size_t)r0 * SKC + kb);
                afr[mt][1] = *(const uint32_t*)(sA + (size_t)(r0 + 8) * SKC + kb);
                afr[mt][2] = *(const uint32_t*)(sA + (size_t)r0 * SKC + kb + 8);
                afr[mt][3] = *(const uint32_t*)(sA + (size_t)(r0 + 8) * SKC + kb + 8);
            }
            uint32_t bfr[8][2];
            #pragma unroll
            for (int n = 0; n < 8; n++) {
                int nr = wn * 64 + n * 8 + (lane >> 2);
                bfr[n][0] = *(const uint32_t*)(sB + (size_t)nr * SKC + kb);
                bfr[n][1] = *(const uint32_t*)(sB + (size_t)nr * SKC + kb + 8);
            }
            #pragma unroll
            for (int mt = 0; mt < 2; mt++)
                #pragma unroll
                for (int n = 0; n < 8; n++)
                    mma_bf16(acc[mt][n], afr[mt], bfr[n]);
        }
    }

    // ---- epilogue ----
    #pragma unroll
    for (int mt = 0; mt < 2; mt++) {
        #pragma unroll
        for (int half = 0; half < 2; half++) {           // c01 (row+0) vs c23 (row+8)
            int gr = bm + wm * 32 + mt * 16 + (lane >> 2) + half * 8;
            if (MODE == 0) {
                const int bb = gr >> 10, nn = gr & 1023;
                #pragma unroll
                for (int n = 0; n < 8; n++) {
                    #pragma unroll
                    for (int e = 0; e < 2; e++) {
                        int gc = bn + wn * 64 + n * 8 + 2 * (lane & 3) + e;
                        float v = acc[mt][n][half * 2 + e] + bias[gc];
                        int h  = gc / 192;
                        int rr = gc - h * 192;
                        int dd = rr / 3;
                        int which = rr - dd * 3;
                        size_t idx = (((size_t)(bb * NHEAD + h)) * SEQ + nn) * DHEAD + dd;
                        if      (which == 0) g_Q[idx] = v;
                        else if (which == 1) g_K[idx] = v;
                        else                 g_V[idx] = v;
                    }
                }
            } else {
                #pragma unroll
                for (int n = 0; n < 8; n++) {
                    int gc = bn + wn * 64 + n * 8 + 2 * (lane & 3);
                    float2 v = make_float2(acc[mt][n][half*2]   + bias[gc],
                                           acc[mt][n][half*2+1] + bias[gc + 1]);
                    *(float2*)(out + (size_t)gr * 1024 + gc) = v;
                }
            }
        }
    }
}

// ------------------------- flash attention (fp32) -------------------------
__global__ __launch_bounds__(128) void flash_attn_kernel()
{
    const int bh   = blockIdx.x;
    const int qt   = blockIdx.y;
    const int tid  = threadIdx.x;
    const int qrow = qt * 128 + tid;

    const float* __restrict__ Qb = g_Q + (size_t)bh * SEQ * DHEAD;
    const float* __restrict__ Kb = g_K + (size_t)bh * SEQ * DHEAD;
    const float* __restrict__ Vb = g_V + (size_t)bh * SEQ * DHEAD;

    float q[64];
    {
        const float4* qp = (const float4*)(Qb + (size_t)qrow * DHEAD);
        #pragma unroll
        for (int c = 0; c < 16; c++) {
            float4 t = qp[c];
            q[4*c] = t.x; q[4*c+1] = t.y; q[4*c+2] = t.z; q[4*c+3] = t.w;
        }
    }
    float o[64];
    #pragma unroll
    for (int i = 0; i < 64; i++) o[i] = 0.f;
    float m = -1e30f, l = 0.f;

    __shared__ float Ks[16][64];
    __shared__ float Vs[16][64];

    for (int t = 0; t < SEQ / 16; t++) {
        __syncthreads();
        {
            const float4* kg = (const float4*)(Kb + (size_t)t * 16 * DHEAD);
            const float4* vg = (const float4*)(Vb + (size_t)t * 16 * DHEAD);
            float4* ks = (float4*)(&Ks[0][0]);
            float4* vs = (float4*)(&Vs[0][0]);
            ks[tid]       = kg[tid];
            ks[tid + 128] = kg[tid + 128];
            vs[tid]       = vg[tid];
            vs[tid + 128] = vg[tid + 128];
        }
        __syncthreads();

        float s[16];
        #pragma unroll
        for (int j = 0; j < 16; j++) {
            float s0 = 0.f, s1 = 0.f, s2 = 0.f, s3 = 0.f;
            const float4* kr = (const float4*)(&Ks[j][0]);
            #pragma unroll
            for (int c = 0; c < 16; c++) {
                float4 kv = kr[c];
                s0 += q[4*c]     * kv.x;
                s1 += q[4*c + 1] * kv.y;
                s2 += q[4*c + 2] * kv.z;
                s3 += q[4*c + 3] * kv.w;
            }
            s[j] = (s0 + s1) + (s2 + s3);
        }
        float tmax = s[0];
        #pragma unroll
        for (int j = 1; j < 16; j++) tmax = fmaxf(tmax, s[j]);
        float nm    = fmaxf(m, tmax);
        float alpha = __expf(m - nm);
        float psum  = 0.f;
        #pragma unroll
        for (int j = 0; j < 16; j++) { s[j] = __expf(s[j] - nm); psum += s[j]; }
        l = l * alpha + psum;
        m = nm;
        #pragma unroll
        for (int dd = 0; dd < 64; dd++) o[dd] *= alpha;
        #pragma unroll
        for (int j = 0; j < 16; j++) {
            float pj = s[j];
            const float4* vr = (const float4*)(&Vs[j][0]);
            #pragma unroll
            for (int c = 0; c < 16; c++) {
                float4 vv = vr[c];
                o[4*c]     += pj * vv.x;
                o[4*c + 1] += pj * vv.y;
                o[4*c + 2] += pj * vv.z;
                o[4*c + 3] += pj * vv.w;
            }
        }
    }

    const float inv = 1.0f / (l * 32.0f);
    const int bb = bh >> 4;
    const int hh = bh & 15;
    size_t ob = ((size_t)(bb * SEQ + qrow)) * DEMB + hh * DHEAD;
    __nv_bfloat162* oh = (__nv_bfloat162*)(g_Ohi + ob);
    __nv_bfloat162* ol = (__nv_bfloat162*)(g_Olo + ob);
    #pragma unroll
    for (int c = 0; c < 32; c++) {
        float v0 = o[2*c] * inv, v1 = o[2*c+1] * inv;
        __nv_bfloat16 h0,l0,h1,l1;
        split2(v0,h0,l0); split2(v1,h1,l1);
        oh[c] = __nv_bfloat162(h0,h1);
        ol[c] = __nv_bfloat162(l0,l1);
    }
}

// ---------------------------------------------------------------------------
extern "C" void kernel_launch(void* const* d_in, const int* in_sizes, int n_in,
                              void* d_out, int out_size)
{
    const float* x      = (const float*)d_in[0];
    const float* w_qkv  = (const float*)d_in[1];
    const float* b_qkv  = (const float*)d_in[2];
    const float* w_proj = (const float*)d_in[3];
    const float* b_proj = (const float*)d_in[4];
    float* out = (float*)d_out;

    // conversions (scratch buffers resolved inside device code)
    cvt_x_kernel<<<8192, 256>>>((const float4*)x);
    cvt_wT_kernel<0><<<dim3(96, 32), dim3(32, 8)>>>(w_qkv);
    cvt_wT_kernel<1><<<dim3(32, 32), dim3(32, 8)>>>(w_proj);

    // qkv GEMM (mma.sync bf16 split): [8192,1024] x [1024,3072]
    gemm_bf16_kernel<0><<<dim3(3072/128, MROWS/128), 256>>>(b_qkv, nullptr);

    // flash attention (fp32), writes Ohi/Olo
    flash_attn_kernel<<<dim3(BATCH*NHEAD, SEQ/128), 128>>>();

    // proj GEMM (mma.sync bf16 split): [8192,1024] x [1024,1024] -> d_out
    gemm_bf16_kernel<1><<<dim3(1024/128, MROWS/128), 256>>>(b_proj, out);
}

// round 8
// speedup vs baseline: 1.2765x; 1.0029x over previous
#include <cuda_runtime.h>
#include <cuda_bf16.h>
#include <stdint.h>
#include <math.h>

#define BATCH 8
#define SEQ   1024
#define DEMB  1024
#define NHEAD 16
#define DHEAD 64
#define MROWS (BATCH*SEQ)   // 8192

// ------------------------- scratch (device globals) -------------------------
__device__ float g_Q[(size_t)BATCH*NHEAD*SEQ*DHEAD];
__device__ float g_K[(size_t)BATCH*NHEAD*SEQ*DHEAD];
__device__ float g_V[(size_t)BATCH*NHEAD*SEQ*DHEAD];

__device__ __align__(16) __nv_bfloat16 g_Xhi[(size_t)MROWS*DEMB];
__device__ __align__(16) __nv_bfloat16 g_Xlo[(size_t)MROWS*DEMB];
__device__ __align__(16) __nv_bfloat16 g_WqThi[(size_t)3072*1024];
__device__ __align__(16) __nv_bfloat16 g_WqTlo[(size_t)3072*1024];
__device__ __align__(16) __nv_bfloat16 g_WpThi[(size_t)1024*1024];
__device__ __align__(16) __nv_bfloat16 g_WpTlo[(size_t)1024*1024];
__device__ __align__(16) __nv_bfloat16 g_Ohi[(size_t)MROWS*DEMB];
__device__ __align__(16) __nv_bfloat16 g_Olo[(size_t)MROWS*DEMB];

// ------------------------- helpers -------------------------
__device__ __forceinline__ void mma_bf16(float* d, const uint32_t* a, const uint32_t* b) {
    asm volatile("mma.sync.aligned.m16n8k16.row.col.f32.bf16.bf16.f32 "
                 "{%0,%1,%2,%3}, {%4,%5,%6,%7}, {%8,%9}, {%0,%1,%2,%3};"
                 : "+f"(d[0]), "+f"(d[1]), "+f"(d[2]), "+f"(d[3])
                 : "r"(a[0]), "r"(a[1]), "r"(a[2]), "r"(a[3]), "r"(b[0]), "r"(b[1]));
}
__device__ __forceinline__ void split2(float v, __nv_bfloat16& h, __nv_bfloat16& l) {
    h = __float2bfloat16(v);
    l = __float2bfloat16(v - __bfloat162float(h));
}

// FMA-pipe exp (MUFU on B300 is 0.5 op/cyc/SM — 256x slower than FMA).
// Valid for x <= 0 (softmax args); rel err ~2e-6.
__device__ __forceinline__ float fast_exp(float x) {
    float y = fmaxf(x * 1.44269504088896340736f, -120.0f);  // log2(e), clamp
    float t = y + 12582912.0f;                // round-to-nearest via 1.5*2^23
    float n = t - 12582912.0f;
    float f = y - n;                          // f in [-0.5, 0.5]
    float p =        1.3333558e-3f;           // exp2(f) Taylor in ln2
    p = fmaf(p, f,   9.6181291e-3f);
    p = fmaf(p, f,   5.5504109e-2f);
    p = fmaf(p, f,   2.4022651e-1f);
    p = fmaf(p, f,   6.9314718e-1f);
    p = fmaf(p, f,   1.0f);
    int e = (int)n;
    float s = __int_as_float((e + 127) << 23);  // 2^n  (n >= -120 guaranteed)
    return p * s;
}

// ------------------------- conversion kernels -------------------------
__global__ __launch_bounds__(256) void cvt_x_kernel(const float4* __restrict__ X)
{
    __nv_bfloat162* hi = (__nv_bfloat162*)g_Xhi;
    __nv_bfloat162* lo = (__nv_bfloat162*)g_Xlo;
    int i = blockIdx.x * 256 + threadIdx.x;   // over 2M float4
    float4 v = X[i];
    __nv_bfloat16 h0,l0,h1,l1,h2,l2,h3,l3;
    split2(v.x,h0,l0); split2(v.y,h1,l1); split2(v.z,h2,l2); split2(v.w,h3,l3);
    hi[2*i]   = __nv_bfloat162(h0,h1); hi[2*i+1] = __nv_bfloat162(h2,h3);
    lo[2*i]   = __nv_bfloat162(l0,l1); lo[2*i+1] = __nv_bfloat162(l2,l3);
}

// W [1024(k), ncols(n)] -> WT hi/lo [ncols, 1024] (n rows, k contiguous)
template<int WSEL>
__global__ __launch_bounds__(256) void cvt_wT_kernel(const float* __restrict__ W)
{
    const int ncols = (WSEL == 0) ? 3072 : 1024;
    __nv_bfloat16* hiT = (WSEL == 0) ? g_WqThi : g_WpThi;
    __nv_bfloat16* loT = (WSEL == 0) ? g_WqTlo : g_WpTlo;

    __shared__ float t[32][33];
    const int n0 = blockIdx.x * 32, k0 = blockIdx.y * 32;
    const int tx = threadIdx.x, ty = threadIdx.y;   // (32, 8)
    #pragma unroll
    for (int r = ty; r < 32; r += 8)
        t[r][tx] = W[(size_t)(k0 + r) * ncols + n0 + tx];
    __syncthreads();
    #pragma unroll
    for (int rr = ty; rr < 32; rr += 8) {
        float v = t[tx][rr];
        __nv_bfloat16 h, l; split2(v, h, l);
        size_t o = (size_t)(n0 + rr) * 1024 + k0 + tx;
        hiT[o] = h; loT[o] = l;
    }
}

// ------------------------- mma.sync split-bf16 GEMM -------------------------
// C = Ahi*Bhi + Ahi*Blo + Alo*Bhi over K=1024 (3 passes x 16 chunks of K=64).
// Double-buffered smem, ONE barrier per chunk; register prefetch of next chunk.
#define KC    64
#define SKC   72                  // padded smem row stride (elements)
#define HALFE (128*SKC)           // elems per matrix per buffer
#define NCH   48                  // 3 passes x 16 chunks
#define GDYN  (4*HALFE*2)         // bytes: 2 buffers x (A+B) = 73728

template<int MODE>   // 0: qkv (A=X, B=WqT, scatter), 1: proj (A=O, B=WpT, store)
__global__ __launch_bounds__(256, 1) void gemm_bf16_kernel(
    const float* __restrict__ bias, float* __restrict__ out)
{
    const __nv_bfloat16* __restrict__ Ahi = (MODE == 0) ? g_Xhi   : g_Ohi;
    const __nv_bfloat16* __restrict__ Alo = (MODE == 0) ? g_Xlo   : g_Olo;
    const __nv_bfloat16* __restrict__ Bhi = (MODE == 0) ? g_WqThi : g_WpThi;
    const __nv_bfloat16* __restrict__ Blo = (MODE == 0) ? g_WqTlo : g_WpTlo;

    extern __shared__ __align__(16) __nv_bfloat16 smem_dyn[];

    const int tid  = threadIdx.x;
    const int wid  = tid >> 5, lane = tid & 31;
    const int wm   = wid & 3;
    const int wn   = wid >> 2;
    const int bn   = blockIdx.x * 128;
    const int bm   = blockIdx.y * 128;

    float acc[2][8][4];
    #pragma unroll
    for (int mt = 0; mt < 2; mt++)
        #pragma unroll
        for (int n = 0; n < 8; n++)
            #pragma unroll
            for (int c = 0; c < 4; c++) acc[mt][n][c] = 0.f;

    uint4 ra[4], rb[4];
    auto issue_loads = [&](int i) {
        const int p  = i >> 4;                  // 0: hi*hi, 1: hi*lo, 2: lo*hi
        const int k0 = (i & 15) * KC;
        const __nv_bfloat16* Ap = (p == 2) ? Alo : Ahi;
        const __nv_bfloat16* Bp = (p == 1) ? Blo : Bhi;
        #pragma unroll
        for (int q = 0; q < 4; q++) {
            int idx = q * 256 + tid;
            int row = idx >> 3;
            int col = (idx & 7) * 8;
            ra[q] = *(const uint4*)(Ap + (size_t)(bm + row) * 1024 + k0 + col);
            rb[q] = *(const uint4*)(Bp + (size_t)(bn + row) * 1024 + k0 + col);
        }
    };
    issue_loads(0);

    for (int i = 0; i < NCH; i++) {
        const int bsel = i & 1;
        __nv_bfloat16* sA = smem_dyn + bsel * 2 * HALFE;
        __nv_bfloat16* sB = sA + HALFE;

        // store current chunk (regs) into this buffer; prefetch next chunk
        #pragma unroll
        for (int q = 0; q < 4; q++) {
            int idx = q * 256 + tid;
            int row = idx >> 3;
            int col = (idx & 7) * 8;
            *(uint4*)(sA + row * SKC + col) = ra[q];
            *(uint4*)(sB + row * SKC + col) = rb[q];
        }
        if (i + 1 < NCH) issue_loads(i + 1);
        __syncthreads();    // single barrier per chunk (buffer parity protects reads)

        #pragma unroll
        for (int ks = 0; ks < 4; ks++) {
            const int kb = ks * 16 + (lane & 3) * 2;
            uint32_t afr[2][4];
            #pragma unroll
            for (int mt = 0; mt < 2; mt++) {
                int r0 = wm * 32 + mt * 16 + (lane >> 2);
                afr[mt][0] = *(const uint32_t*)(sA + (size_t)r0 * SKC + kb);
                afr[mt][1] = *(const uint32_t*)(sA + (size_t)(r0 + 8) * SKC + kb);
                afr[mt][2] = *(const uint32_t*)(sA + (size_t)r0 * SKC + kb + 8);
                afr[mt][3] = *(const uint32_t*)(sA + (size_t)(r0 + 8) * SKC + kb + 8);
            }
            uint32_t bfr[8][2];
            #pragma unroll
            for (int n = 0; n < 8; n++) {
                int nr = wn * 64 + n * 8 + (lane >> 2);
                bfr[n][0] = *(const uint32_t*)(sB + (size_t)nr * SKC + kb);
                bfr[n][1] = *(const uint32_t*)(sB + (size_t)nr * SKC + kb + 8);
            }
            #pragma unroll
            for (int mt = 0; mt < 2; mt++)
                #pragma unroll
                for (int n = 0; n < 8; n++)
                    mma_bf16(acc[mt][n], afr[mt], bfr[n]);
        }
    }

    // ---- epilogue ----
    #pragma unroll
    for (int mt = 0; mt < 2; mt++) {
        #pragma unroll
        for (int half = 0; half < 2; half++) {
            int gr = bm + wm * 32 + mt * 16 + (lane >> 2) + half * 8;
            if (MODE == 0) {
                const int bb = gr >> 10, nn = gr & 1023;
                #pragma unroll
                for (int n = 0; n < 8; n++) {
                    #pragma unroll
                    for (int e = 0; e < 2; e++) {
                        int gc = bn + wn * 64 + n * 8 + 2 * (lane & 3) + e;
                        float v = acc[mt][n][half * 2 + e] + bias[gc];
                        int h  = gc / 192;
                        int rr = gc - h * 192;
                        int dd = rr / 3;
                        int which = rr - dd * 3;
                        size_t idx = (((size_t)(bb * NHEAD + h)) * SEQ + nn) * DHEAD + dd;
                        if      (which == 0) g_Q[idx] = v;
                        else if (which == 1) g_K[idx] = v;
                        else                 g_V[idx] = v;
                    }
                }
            } else {
                #pragma unroll
                for (int n = 0; n < 8; n++) {
                    int gc = bn + wn * 64 + n * 8 + 2 * (lane & 3);
                    float2 v = make_float2(acc[mt][n][half*2]   + bias[gc],
                                           acc[mt][n][half*2+1] + bias[gc + 1]);
                    *(float2*)(out + (size_t)gr * 1024 + gc) = v;
                }
            }
        }
    }
}

// ------------------------- flash attention (fp32, FMA-pipe exp) -------------------------
__global__ __launch_bounds__(128) void flash_attn_kernel()
{
    const int bh   = blockIdx.x;
    const int qt   = blockIdx.y;
    const int tid  = threadIdx.x;
    const int qrow = qt * 128 + tid;

    const float* __restrict__ Qb = g_Q + (size_t)bh * SEQ * DHEAD;
    const float* __restrict__ Kb = g_K + (size_t)bh * SEQ * DHEAD;
    const float* __restrict__ Vb = g_V + (size_t)bh * SEQ * DHEAD;

    float q[64];
    {
        const float4* qp = (const float4*)(Qb + (size_t)qrow * DHEAD);
        #pragma unroll
        for (int c = 0; c < 16; c++) {
            float4 t = qp[c];
            q[4*c] = t.x; q[4*c+1] = t.y; q[4*c+2] = t.z; q[4*c+3] = t.w;
        }
    }
    float o[64];
    #pragma unroll
    for (int i = 0; i < 64; i++) o[i] = 0.f;
    // m = 0 init: keeps all exp args finite & <= ~0 (valid online softmax upper bound)
    float m = 0.0f, l = 0.f;

    __shared__ float Ks[16][64];
    __shared__ float Vs[16][64];

    for (int t = 0; t < SEQ / 16; t++) {
        __syncthreads();
        {
            const float4* kg = (const float4*)(Kb + (size_t)t * 16 * DHEAD);
            const float4* vg = (const float4*)(Vb + (size_t)t * 16 * DHEAD);
            float4* ks = (float4*)(&Ks[0][0]);
            float4* vs = (float4*)(&Vs[0][0]);
            ks[tid]       = kg[tid];
            ks[tid + 128] = kg[tid + 128];
            vs[tid]       = vg[tid];
            vs[tid + 128] = vg[tid + 128];
        }
        __syncthreads();

        float s[16];
        #pragma unroll
        for (int j = 0; j < 16; j++) {
            float s0 = 0.f, s1 = 0.f, s2 = 0.f, s3 = 0.f;
            const float4* kr = (const float4*)(&Ks[j][0]);
            #pragma unroll
            for (int c = 0; c < 16; c++) {
                float4 kv = kr[c];
                s0 += q[4*c]     * kv.x;
                s1 += q[4*c + 1] * kv.y;
                s2 += q[4*c + 2] * kv.z;
                s3 += q[4*c + 3] * kv.w;
            }
            s[j] = (s0 + s1) + (s2 + s3);
        }
        float tmax = s[0];
        #pragma unroll
        for (int j = 1; j < 16; j++) tmax = fmaxf(tmax, s[j]);
        float nm    = fmaxf(m, tmax);
        float alpha = fast_exp(m - nm);
        float psum  = 0.f;
        #pragma unroll
        for (int j = 0; j < 16; j++) { s[j] = fast_exp(s[j] - nm); psum += s[j]; }
        l = l * alpha + psum;
        m = nm;
        #pragma unroll
        for (int dd = 0; dd < 64; dd++) o[dd] *= alpha;
        #pragma unroll
        for (int j = 0; j < 16; j++) {
            float pj = s[j];
            const float4* vr = (const float4*)(&Vs[j][0]);
            #pragma unroll
            for (int c = 0; c < 16; c++) {
                float4 vv = vr[c];
                o[4*c]     += pj * vv.x;
                o[4*c + 1] += pj * vv.y;
                o[4*c + 2] += pj * vv.z;
                o[4*c + 3] += pj * vv.w;
            }
        }
    }

    const float inv = 1.0f / (l * 32.0f);
    const int bb = bh >> 4;
    const int hh = bh & 15;
    size_t ob = ((size_t)(bb * SEQ + qrow)) * DEMB + hh * DHEAD;
    __nv_bfloat162* oh = (__nv_bfloat162*)(g_Ohi + ob);
    __nv_bfloat162* ol = (__nv_bfloat162*)(g_Olo + ob);
    #pragma unroll
    for (int c = 0; c < 32; c++) {
        float v0 = o[2*c] * inv, v1 = o[2*c+1] * inv;
        __nv_bfloat16 h0,l0,h1,l1;
        split2(v0,h0,l0); split2(v1,h1,l1);
        oh[c] = __nv_bfloat162(h0,h1);
        ol[c] = __nv_bfloat162(l0,l1);
    }
}

// ---------------------------------------------------------------------------
extern "C" void kernel_launch(void* const* d_in, const int* in_sizes, int n_in,
                              void* d_out, int out_size)
{
    const float* x      = (const float*)d_in[0];
    const float* w_qkv  = (const float*)d_in[1];
    const float* b_qkv  = (const float*)d_in[2];
    const float* w_proj = (const float*)d_in[3];
    const float* b_proj = (const float*)d_in[4];
    float* out = (float*)d_out;

    static int attr_set = 0;
    if (!attr_set) {
        cudaFuncSetAttribute(gemm_bf16_kernel<0>, cudaFuncAttributeMaxDynamicSharedMemorySize, GDYN);
        cudaFuncSetAttribute(gemm_bf16_kernel<1>, cudaFuncAttributeMaxDynamicSharedMemorySize, GDYN);
        attr_set = 1;
    }

    cvt_x_kernel<<<8192, 256>>>((const float4*)x);
    cvt_wT_kernel<0><<<dim3(96, 32), dim3(32, 8)>>>(w_qkv);
    cvt_wT_kernel<1><<<dim3(32, 32), dim3(32, 8)>>>(w_proj);

    gemm_bf16_kernel<0><<<dim3(3072/128, MROWS/128), 256, GDYN>>>(b_qkv, nullptr);

    flash_attn_kernel<<<dim3(BATCH*NHEAD, SEQ/128), 128>>>();

    gemm_bf16_kernel<1><<<dim3(1024/128, MROWS/128), 256, GDYN>>>(b_proj, out);
}

// round 9
// speedup vs baseline: 2.2905x; 1.7943x over previous
#include <cuda_runtime.h>
#include <cuda_bf16.h>
#include <stdint.h>
#include <math.h>

#define BATCH 8
#define SEQ   1024
#define DEMB  1024
#define NHEAD 16
#define DHEAD 64
#define MROWS (BATCH*SEQ)   // 8192

// ------------------------- scratch (device globals) -------------------------
__device__ __align__(16) __nv_bfloat16 g_Qhi[(size_t)BATCH*NHEAD*SEQ*DHEAD];
__device__ __align__(16) __nv_bfloat16 g_Qlo[(size_t)BATCH*NHEAD*SEQ*DHEAD];
__device__ __align__(16) __nv_bfloat16 g_Khi[(size_t)BATCH*NHEAD*SEQ*DHEAD];
__device__ __align__(16) __nv_bfloat16 g_Klo[(size_t)BATCH*NHEAD*SEQ*DHEAD];
__device__ __align__(16) __nv_bfloat16 g_Vthi[(size_t)BATCH*NHEAD*DHEAD*SEQ];  // [B,H,64,N]
__device__ __align__(16) __nv_bfloat16 g_Vtlo[(size_t)BATCH*NHEAD*DHEAD*SEQ];

__device__ __align__(16) __nv_bfloat16 g_Xhi[(size_t)MROWS*DEMB];
__device__ __align__(16) __nv_bfloat16 g_Xlo[(size_t)MROWS*DEMB];
__device__ __align__(16) __nv_bfloat16 g_WqThi[(size_t)3072*1024];
__device__ __align__(16) __nv_bfloat16 g_WqTlo[(size_t)3072*1024];
__device__ __align__(16) __nv_bfloat16 g_WpThi[(size_t)1024*1024];
__device__ __align__(16) __nv_bfloat16 g_WpTlo[(size_t)1024*1024];
__device__ __align__(16) __nv_bfloat16 g_Ohi[(size_t)MROWS*DEMB];
__device__ __align__(16) __nv_bfloat16 g_Olo[(size_t)MROWS*DEMB];

// ------------------------- helpers -------------------------
__device__ __forceinline__ void mma_bf16(float* d, const uint32_t* a, const uint32_t* b) {
    asm volatile("mma.sync.aligned.m16n8k16.row.col.f32.bf16.bf16.f32 "
                 "{%0,%1,%2,%3}, {%4,%5,%6,%7}, {%8,%9}, {%0,%1,%2,%3};"
                 : "+f"(d[0]), "+f"(d[1]), "+f"(d[2]), "+f"(d[3])
                 : "r"(a[0]), "r"(a[1]), "r"(a[2]), "r"(a[3]), "r"(b[0]), "r"(b[1]));
}
__device__ __forceinline__ void split2(float v, __nv_bfloat16& h, __nv_bfloat16& l) {
    h = __float2bfloat16(v);
    l = __float2bfloat16(v - __bfloat162float(h));
}
// pack (x,y) into bf16x2 hi + bf16x2 lo words
__device__ __forceinline__ void pack_split(float x, float y, uint32_t& hi, uint32_t& lo) {
    __nv_bfloat16 xh, xl, yh, yl;
    split2(x, xh, xl); split2(y, yh, yl);
    __nv_bfloat162 h2(xh, yh), l2(xl, yl);
    hi = *(uint32_t*)&h2; lo = *(uint32_t*)&l2;
}
// FMA-pipe exp; valid for x <= 0; rel err ~2e-6.
__device__ __forceinline__ float fast_exp(float x) {
    float y = fmaxf(x * 1.44269504088896340736f, -120.0f);
    float t = y + 12582912.0f;
    float n = t - 12582912.0f;
    float f = y - n;
    float p =        1.3333558e-3f;
    p = fmaf(p, f,   9.6181291e-3f);
    p = fmaf(p, f,   5.5504109e-2f);
    p = fmaf(p, f,   2.4022651e-1f);
    p = fmaf(p, f,   6.9314718e-1f);
    p = fmaf(p, f,   1.0f);
    int e = (int)n;
    float s = __int_as_float((e + 127) << 23);
    return p * s;
}

// ------------------------- conversion kernels -------------------------
__global__ __launch_bounds__(256) void cvt_x_kernel(const float4* __restrict__ X)
{
    __nv_bfloat162* hi = (__nv_bfloat162*)g_Xhi;
    __nv_bfloat162* lo = (__nv_bfloat162*)g_Xlo;
    int i = blockIdx.x * 256 + threadIdx.x;
    float4 v = X[i];
    __nv_bfloat16 h0,l0,h1,l1,h2,l2,h3,l3;
    split2(v.x,h0,l0); split2(v.y,h1,l1); split2(v.z,h2,l2); split2(v.w,h3,l3);
    hi[2*i]   = __nv_bfloat162(h0,h1); hi[2*i+1] = __nv_bfloat162(h2,h3);
    lo[2*i]   = __nv_bfloat162(l0,l1); lo[2*i+1] = __nv_bfloat162(l2,l3);
}

template<int WSEL>
__global__ __launch_bounds__(256) void cvt_wT_kernel(const float* __restrict__ W)
{
    const int ncols = (WSEL == 0) ? 3072 : 1024;
    __nv_bfloat16* hiT = (WSEL == 0) ? g_WqThi : g_WpThi;
    __nv_bfloat16* loT = (WSEL == 0) ? g_WqTlo : g_WpTlo;

    __shared__ float t[32][33];
    const int n0 = blockIdx.x * 32, k0 = blockIdx.y * 32;
    const int tx = threadIdx.x, ty = threadIdx.y;
    #pragma unroll
    for (int r = ty; r < 32; r += 8)
        t[r][tx] = W[(size_t)(k0 + r) * ncols + n0 + tx];
    __syncthreads();
    #pragma unroll
    for (int rr = ty; rr < 32; rr += 8) {
        float v = t[tx][rr];
        __nv_bfloat16 h, l; split2(v, h, l);
        size_t o = (size_t)(n0 + rr) * 1024 + k0 + tx;
        hiT[o] = h; loT[o] = l;
    }
}

// ------------------------- mma.sync split-bf16 GEMM (unchanged core) ---------
#define KC    64
#define SKC   72
#define HALFE (128*SKC)
#define NCH   48
#define GDYN  (4*HALFE*2)

template<int MODE>   // 0: qkv (scatter hi/lo Q,K,Vt), 1: proj (store fp32)
__global__ __launch_bounds__(256, 1) void gemm_bf16_kernel(
    const float* __restrict__ bias, float* __restrict__ out)
{
    const __nv_bfloat16* __restrict__ Ahi = (MODE == 0) ? g_Xhi   : g_Ohi;
    const __nv_bfloat16* __restrict__ Alo = (MODE == 0) ? g_Xlo   : g_Olo;
    const __nv_bfloat16* __restrict__ Bhi = (MODE == 0) ? g_WqThi : g_WpThi;
    const __nv_bfloat16* __restrict__ Blo = (MODE == 0) ? g_WqTlo : g_WpTlo;

    extern __shared__ __align__(16) __nv_bfloat16 smem_dyn[];

    const int tid  = threadIdx.x;
    const int wid  = tid >> 5, lane = tid & 31;
    const int wm   = wid & 3;
    const int wn   = wid >> 2;
    const int bn   = blockIdx.x * 128;
    const int bm   = blockIdx.y * 128;

    float acc[2][8][4];
    #pragma unroll
    for (int mt = 0; mt < 2; mt++)
        #pragma unroll
        for (int n = 0; n < 8; n++)
            #pragma unroll
            for (int c = 0; c < 4; c++) acc[mt][n][c] = 0.f;

    uint4 ra[4], rb[4];
    auto issue_loads = [&](int i) {
        const int p  = i >> 4;
        const int k0 = (i & 15) * KC;
        const __nv_bfloat16* Ap = (p == 2) ? Alo : Ahi;
        const __nv_bfloat16* Bp = (p == 1) ? Blo : Bhi;
        #pragma unroll
        for (int q = 0; q < 4; q++) {
            int idx = q * 256 + tid;
            int row = idx >> 3;
            int col = (idx & 7) * 8;
            ra[q] = *(const uint4*)(Ap + (size_t)(bm + row) * 1024 + k0 + col);
            rb[q] = *(const uint4*)(Bp + (size_t)(bn + row) * 1024 + k0 + col);
        }
    };
    issue_loads(0);

    for (int i = 0; i < NCH; i++) {
        const int bsel = i & 1;
        __nv_bfloat16* sA = smem_dyn + bsel * 2 * HALFE;
        __nv_bfloat16* sB = sA + HALFE;

        #pragma unroll
        for (int q = 0; q < 4; q++) {
            int idx = q * 256 + tid;
            int row = idx >> 3;
            int col = (idx & 7) * 8;
            *(uint4*)(sA + row * SKC + col) = ra[q];
            *(uint4*)(sB + row * SKC + col) = rb[q];
        }
        if (i + 1 < NCH) issue_loads(i + 1);
        __syncthreads();

        #pragma unroll
        for (int ks = 0; ks < 4; ks++) {
            const int kb = ks * 16 + (lane & 3) * 2;
            uint32_t afr[2][4];
            #pragma unroll
            for (int mt = 0; mt < 2; mt++) {
                int r0 = wm * 32 + mt * 16 + (lane >> 2);
                afr[mt][0] = *(const uint32_t*)(sA + (size_t)r0 * SKC + kb);
                afr[mt][1] = *(const uint32_t*)(sA + (size_t)(r0 + 8) * SKC + kb);
                afr[mt][2] = *(const uint32_t*)(sA + (size_t)r0 * SKC + kb + 8);
                afr[mt][3] = *(const uint32_t*)(sA + (size_t)(r0 + 8) * SKC + kb + 8);
            }
            uint32_t bfr[8][2];
            #pragma unroll
            for (int n = 0; n < 8; n++) {
                int nr = wn * 64 + n * 8 + (lane >> 2);
                bfr[n][0] = *(const uint32_t*)(sB + (size_t)nr * SKC + kb);
                bfr[n][1] = *(const uint32_t*)(sB + (size_t)nr * SKC + kb + 8);
            }
            #pragma unroll
            for (int mt = 0; mt < 2; mt++)
                #pragma unroll
                for (int n = 0; n < 8; n++)
                    mma_bf16(acc[mt][n], afr[mt], bfr[n]);
        }
    }

    // ---- epilogue ----
    #pragma unroll
    for (int mt = 0; mt < 2; mt++) {
        #pragma unroll
        for (int half = 0; half < 2; half++) {
            int gr = bm + wm * 32 + mt * 16 + (lane >> 2) + half * 8;
            if (MODE == 0) {
                const int bb = gr >> 10, nn = gr & 1023;
                #pragma unroll
                for (int n = 0; n < 8; n++) {
                    #pragma unroll
                    for (int e = 0; e < 2; e++) {
                        int gc = bn + wn * 64 + n * 8 + 2 * (lane & 3) + e;
                        float v = acc[mt][n][half * 2 + e] + bias[gc];
                        int h  = gc / 192;
                        int rr = gc - h * 192;
                        int dd = rr / 3;
                        int which = rr - dd * 3;
                        __nv_bfloat16 vh, vl; split2(v, vh, vl);
                        if (which == 2) {
                            size_t idx = ((size_t)(bb * NHEAD + h) * DHEAD + dd) * SEQ + nn;
                            g_Vthi[idx] = vh; g_Vtlo[idx] = vl;
                        } else {
                            size_t idx = ((size_t)(bb * NHEAD + h) * SEQ + nn) * DHEAD + dd;
                            if (which == 0) { g_Qhi[idx] = vh; g_Qlo[idx] = vl; }
                            else            { g_Khi[idx] = vh; g_Klo[idx] = vl; }
                        }
                    }
                }
            } else {
                #pragma unroll
                for (int n = 0; n < 8; n++) {
                    int gc = bn + wn * 64 + n * 8 + 2 * (lane & 3);
                    float2 v = make_float2(acc[mt][n][half*2]   + bias[gc],
                                           acc[mt][n][half*2+1] + bias[gc + 1]);
                    *(float2*)(out + (size_t)gr * 1024 + gc) = v;
                }
            }
        }
    }
}

// ------------------------- tensor-core flash attention ----------------------
// Block: 128 queries of one (b,h); 8 warps, warp = m16 x n64.
// Key tiles of 64; S in registers; P frags built from S regs (C-layout == A-half-layout).
// 3-pass split on both QK^T and P*V. Double-buffered smem, reg prefetch, 1 barrier/tile.
#define FSKC 72
#define FMAT (64*FSKC)       // elems per matrix tile in smem
#define FBUF (4*FMAT)        // Khi,Klo,Vthi,Vtlo
#define FDYN (FBUF*2*2)      // bytes (2 buffers, bf16) = 73728

__global__ __launch_bounds__(256, 1) void flash_tc_kernel()
{
    extern __shared__ __align__(16) __nv_bfloat16 fsm[];
    const int tid  = threadIdx.x;
    const int wid  = tid >> 5, lane = tid & 31;
    const int bh   = blockIdx.x;                       // b*16+h
    const int qr   = blockIdx.y * 128 + wid * 16 + (lane >> 2);  // row0
    const int qc   = (lane & 3) * 2;

    // persistent Q fragments (hi/lo), loaded once
    uint32_t qh[4][4], ql[4][4];
    {
        const __nv_bfloat16* Qh = g_Qhi + ((size_t)bh * SEQ + qr) * DHEAD;
        const __nv_bfloat16* Ql = g_Qlo + ((size_t)bh * SEQ + qr) * DHEAD;
        #pragma unroll
        for (int kk = 0; kk < 4; kk++) {
            int c = kk * 16 + qc;
            qh[kk][0] = *(const uint32_t*)(Qh + c);
            qh[kk][1] = *(const uint32_t*)(Qh + 8 * DHEAD + c);
            qh[kk][2] = *(const uint32_t*)(Qh + c + 8);
            qh[kk][3] = *(const uint32_t*)(Qh + 8 * DHEAD + c + 8);
            ql[kk][0] = *(const uint32_t*)(Ql + c);
            ql[kk][1] = *(const uint32_t*)(Ql + 8 * DHEAD + c);
            ql[kk][2] = *(const uint32_t*)(Ql + c + 8);
            ql[kk][3] = *(const uint32_t*)(Ql + 8 * DHEAD + c + 8);
        }
    }

    float o[8][4];
    #pragma unroll
    for (int n = 0; n < 8; n++)
        #pragma unroll
        for (int c = 0; c < 4; c++) o[n][c] = 0.f;
    float m0 = 0.f, m1 = 0.f, l0 = 0.f, l1 = 0.f;

    uint4 pre[8];
    auto issue_load = [&](int t) {
        const int key0 = t * 64;
        #pragma unroll
        for (int i = 0; i < 2; i++) {
            int u = i * 256 + tid;
            int row = u >> 3, c8 = (u & 7) * 8;
            size_t koff = ((size_t)bh * SEQ + key0 + row) * DHEAD + c8;
            size_t voff = ((size_t)bh * DHEAD + row) * SEQ + key0 + c8;
            pre[i]     = *(const uint4*)(g_Khi  + koff);
            pre[2 + i] = *(const uint4*)(g_Klo  + koff);
            pre[4 + i] = *(const uint4*)(g_Vthi + voff);
            pre[6 + i] = *(const uint4*)(g_Vtlo + voff);
        }
    };
    issue_load(0);

    for (int t = 0; t < SEQ / 64; t++) {
        __nv_bfloat16* buf = fsm + (t & 1) * FBUF;
        __nv_bfloat16* sKh = buf;
        __nv_bfloat16* sKl = buf + FMAT;
        __nv_bfloat16* sVh = buf + 2 * FMAT;
        __nv_bfloat16* sVl = buf + 3 * FMAT;

        #pragma unroll
        for (int i = 0; i < 2; i++) {
            int u = i * 256 + tid;
            int row = u >> 3, c8 = (u & 7) * 8;
            *(uint4*)(sKh + row * FSKC + c8) = pre[i];
            *(uint4*)(sKl + row * FSKC + c8) = pre[2 + i];
            *(uint4*)(sVh + row * FSKC + c8) = pre[4 + i];
            *(uint4*)(sVl + row * FSKC + c8) = pre[6 + i];
        }
        if (t + 1 < SEQ / 64) issue_load(t + 1);
        __syncthreads();

        // ---- scores: S = Qhi*Khi + Qlo*Khi + Qhi*Klo ----
        float S[8][4];
        #pragma unroll
        for (int n = 0; n < 8; n++)
            #pragma unroll
            for (int c = 0; c < 4; c++) S[n][c] = 0.f;

        #pragma unroll
        for (int kk = 0; kk < 4; kk++) {
            const int kb = kk * 16 + qc;
            uint32_t kf[8][2];
            #pragma unroll
            for (int n = 0; n < 8; n++) {
                int nr = n * 8 + (lane >> 2);
                kf[n][0] = *(const uint32_t*)(sKh + nr * FSKC + kb);
                kf[n][1] = *(const uint32_t*)(sKh + nr * FSKC + kb + 8);
            }
            #pragma unroll
            for (int n = 0; n < 8; n++) {
                mma_bf16(S[n], qh[kk], kf[n]);
                mma_bf16(S[n], ql[kk], kf[n]);
            }
            #pragma unroll
            for (int n = 0; n < 8; n++) {
                int nr = n * 8 + (lane >> 2);
                kf[n][0] = *(const uint32_t*)(sKl + nr * FSKC + kb);
                kf[n][1] = *(const uint32_t*)(sKl + nr * FSKC + kb + 8);
            }
            #pragma unroll
            for (int n = 0; n < 8; n++)
                mma_bf16(S[n], qh[kk], kf[n]);
        }

        // ---- online softmax (rows r0 and r0+8) ----
        float tm0 = S[0][0], tm1 = S[0][2];
        #pragma unroll
        for (int n = 0; n < 8; n++) {
            tm0 = fmaxf(tm0, fmaxf(S[n][0], S[n][1]));
            tm1 = fmaxf(tm1, fmaxf(S[n][2], S[n][3]));
        }
        tm0 = fmaxf(tm0, __shfl_xor_sync(0xffffffffu, tm0, 1));
        tm0 = fmaxf(tm0, __shfl_xor_sync(0xffffffffu, tm0, 2));
        tm1 = fmaxf(tm1, __shfl_xor_sync(0xffffffffu, tm1, 1));
        tm1 = fmaxf(tm1, __shfl_xor_sync(0xffffffffu, tm1, 2));
        float nm0 = fmaxf(m0, tm0), nm1 = fmaxf(m1, tm1);
        float a0 = fast_exp(m0 - nm0), a1 = fast_exp(m1 - nm1);
        m0 = nm0; m1 = nm1;
        float ps0 = 0.f, ps1 = 0.f;
        #pragma unroll
        for (int n = 0; n < 8; n++) {
            S[n][0] = fast_exp(S[n][0] - nm0); ps0 += S[n][0];
            S[n][1] = fast_exp(S[n][1] - nm0); ps0 += S[n][1];
            S[n][2] = fast_exp(S[n][2] - nm1); ps1 += S[n][2];
            S[n][3] = fast_exp(S[n][3] - nm1); ps1 += S[n][3];
        }
        ps0 += __shfl_xor_sync(0xffffffffu, ps0, 1);
        ps0 += __shfl_xor_sync(0xffffffffu, ps0, 2);
        ps1 += __shfl_xor_sync(0xffffffffu, ps1, 1);
        ps1 += __shfl_xor_sync(0xffffffffu, ps1, 2);
        l0 = l0 * a0 + ps0;
        l1 = l1 * a1 + ps1;
        #pragma unroll
        for (int n = 0; n < 8; n++) {
            o[n][0] *= a0; o[n][1] *= a0;
            o[n][2] *= a1; o[n][3] *= a1;
        }

        // ---- PV: o += Phi*Vhi + Plo*Vhi + Phi*Vlo ----
        #pragma unroll
        for (int kk = 0; kk < 4; kk++) {
            uint32_t ph[4], pl[4];
            pack_split(S[2*kk][0],   S[2*kk][1],   ph[0], pl[0]);
            pack_split(S[2*kk][2],   S[2*kk][3],   ph[1], pl[1]);
            pack_split(S[2*kk+1][0], S[2*kk+1][1], ph[2], pl[2]);
            pack_split(S[2*kk+1][2], S[2*kk+1][3], ph[3], pl[3]);

            const int kb = kk * 16 + qc;
            uint32_t vf[8][2];
            #pragma unroll
            for (int n = 0; n < 8; n++) {
                int nr = n * 8 + (lane >> 2);
                vf[n][0] = *(const uint32_t*)(sVh + nr * FSKC + kb);
                vf[n][1] = *(const uint32_t*)(sVh + nr * FSKC + kb + 8);
            }
            #pragma unroll
            for (int n = 0; n < 8; n++) {
                mma_bf16(o[n], ph, vf[n]);
                mma_bf16(o[n], pl, vf[n]);
            }
            #pragma unroll
            for (int n = 0; n < 8; n++) {
                int nr = n * 8 + (lane >> 2);
                vf[n][0] = *(const uint32_t*)(sVl + nr * FSKC + kb);
                vf[n][1] = *(const uint32_t*)(sVl + nr * FSKC + kb + 8);
            }
            #pragma unroll
            for (int n = 0; n < 8; n++)
                mma_bf16(o[n], ph, vf[n]);
        }
    }

    // ---- write O (bf16 hi/lo) as [B*N, D] with column h*64+d ----
    const float inv0 = 1.0f / (l0 * 32.0f);
    const float inv1 = 1.0f / (l1 * 32.0f);
    const int bb = bh >> 4, hh = bh & 15;
    size_t base0 = ((size_t)(bb * SEQ + qr)) * DEMB + hh * DHEAD;
    size_t base1 = base0 + (size_t)8 * DEMB;
    #pragma unroll
    for (int n = 0; n < 8; n++) {
        int col = n * 8 + qc;
        uint32_t h0, l0w, h1, l1w;
        pack_split(o[n][0] * inv0, o[n][1] * inv0, h0, l0w);
        pack_split(o[n][2] * inv1, o[n][3] * inv1, h1, l1w);
        *(uint32_t*)(g_Ohi + base0 + col) = h0;
        *(uint32_t*)(g_Olo + base0 + col) = l0w;
        *(uint32_t*)(g_Ohi + base1 + col) = h1;
        *(uint32_t*)(g_Olo + base1 + col) = l1w;
    }
}

// ---------------------------------------------------------------------------
extern "C" void kernel_launch(void* const* d_in, const int* in_sizes, int n_in,
                              void* d_out, int out_size)
{
    const float* x      = (const float*)d_in[0];
    const float* w_qkv  = (const float*)d_in[1];
    const float* b_qkv  = (const float*)d_in[2];
    const float* w_proj = (const float*)d_in[3];
    const float* b_proj = (const float*)d_in[4];
    float* out = (float*)d_out;

    static int attr_set = 0;
    if (!attr_set) {
        cudaFuncSetAttribute(gemm_bf16_kernel<0>, cudaFuncAttributeMaxDynamicSharedMemorySize, GDYN);
        cudaFuncSetAttribute(gemm_bf16_kernel<1>, cudaFuncAttributeMaxDynamicSharedMemorySize, GDYN);
        cudaFuncSetAttribute(flash_tc_kernel,     cudaFuncAttributeMaxDynamicSharedMemorySize, FDYN);
        attr_set = 1;
    }

    cvt_x_kernel<<<8192, 256>>>((const float4*)x);
    cvt_wT_kernel<0><<<dim3(96, 32), dim3(32, 8)>>>(w_qkv);
    cvt_wT_kernel<1><<<dim3(32, 32), dim3(32, 8)>>>(w_proj);

    gemm_bf16_kernel<0><<<dim3(3072/128, MROWS/128), 256, GDYN>>>(b_qkv, nullptr);

    flash_tc_kernel<<<dim3(BATCH*NHEAD, SEQ/128), 256, FDYN>>>();

    gemm_bf16_kernel<1><<<dim3(1024/128, MROWS/128), 256, GDYN>>>(b_proj, out);
}